// round 17
// baseline (speedup 1.0000x reference)
#include <cuda_runtime.h>
#include <cuda_fp16.h>
#include <cstdint>

// Problem constants (shapes fixed by setup_inputs)
#define NMAX 50000
#define EMAX 800000
#define DD   128
#define RR   8
#define TTY  4
#define TROWS 64                           // conv M-tile
#define TILES64MAX ((NMAX + 63) / 64)      // 782
#define CAP  512                           // per-(r,tile64) bucket capacity

// ---------------- device scratch (no allocations allowed) ----------------
__device__ __half   g_yh[(size_t)NMAX * DD];    // y1 then y2, fp16 (12.8MB, L2-resident)
__device__ float    g_x1[(size_t)NMAX * DD];    // x after conv residual
__device__ int      g_bcnt[RR * TILES64MAX];    // per-(r,tile) bucket counts
__device__ int      g_ebuf[(size_t)RR * TILES64MAX * CAP];  // packed (row<<16)|src
__device__ int      g_tcnt[TTY];
__device__ int      g_perm[TTY * NMAX];         // node ids grouped by type (fixed regions)

// ---------------- helpers ----------------
__device__ __forceinline__ uint32_t pack2(float a, float b) {
    __half2 h = __floats2half2_rn(a, b);
    return *(uint32_t*)&h;
}
__device__ __forceinline__ uint32_t hadd2u(uint32_t a, uint32_t b) {
    __half2 r = __hadd2(*(__half2*)&a, *(__half2*)&b);
    return *(uint32_t*)&r;
}
__device__ __forceinline__ uint32_t smem_u32(const void* p) {
    uint32_t a;
    asm("{ .reg .u64 t; cvta.to.shared.u64 t, %1; cvt.u32.u64 %0, t; }"
        : "=r"(a) : "l"(p));
    return a;
}

__device__ __forceinline__ void mma_f16(float* c,
                                        const uint32_t* a,
                                        uint32_t b0, uint32_t b1) {
    asm volatile(
        "mma.sync.aligned.m16n8k16.row.col.f32.f16.f16.f32 "
        "{%0,%1,%2,%3}, {%4,%5,%6,%7}, {%8,%9}, {%0,%1,%2,%3};\n"
        : "+f"(c[0]), "+f"(c[1]), "+f"(c[2]), "+f"(c[3])
        : "r"(a[0]), "r"(a[1]), "r"(a[2]), "r"(a[3]), "r"(b0), "r"(b1));
}

__device__ __forceinline__ void ldmx4(uint32_t* r, uint32_t addr) {
    asm volatile("ldmatrix.sync.aligned.m8n8.x4.shared.b16 {%0,%1,%2,%3}, [%4];"
        : "=r"(r[0]), "=r"(r[1]), "=r"(r[2]), "=r"(r[3]) : "r"(addr));
}
__device__ __forceinline__ void ldmx4t(uint32_t* r, uint32_t addr) {
    asm volatile("ldmatrix.sync.aligned.m8n8.x4.trans.shared.b16 {%0,%1,%2,%3}, [%4];"
        : "=r"(r[0]), "=r"(r[1]), "=r"(r[2]), "=r"(r[3]) : "r"(addr));
}

// ---------------- small kernels ----------------

__global__ void zero_kernel(int nb) {
    int i = blockIdx.x * blockDim.x + threadIdx.x;
    if (i < nb) g_bcnt[i] = 0;
    if (i < TTY) g_tcnt[i] = 0;
}

// LayerNorm (per-node-type affine) + ReLU -> fp16. One warp per node.
__global__ void ln_relu_kernel(const float* __restrict__ xin,
                               const int*   __restrict__ ntype,
                               const float* __restrict__ gamma,
                               const float* __restrict__ beta,
                               int N, int use_internal) {
    int gwarp = (blockIdx.x * blockDim.x + threadIdx.x) >> 5;
    int lane  = threadIdx.x & 31;
    if (gwarp >= N) return;
    const float* src = use_internal ? g_x1 : xin;
    float4 v = ((const float4*)(src + (size_t)gwarp * DD))[lane];
    float s  = v.x + v.y + v.z + v.w;
    float sq = v.x*v.x + v.y*v.y + v.z*v.z + v.w*v.w;
    #pragma unroll
    for (int d = 16; d; d >>= 1) {
        s  += __shfl_xor_sync(0xFFFFFFFFu, s,  d);
        sq += __shfl_xor_sync(0xFFFFFFFFu, sq, d);
    }
    float mu  = s * (1.0f / DD);
    float var = sq * (1.0f / DD) - mu * mu;
    float rs  = rsqrtf(var + 1e-5f);
    int t = ntype[gwarp];
    float4 g = ((const float4*)(gamma + (size_t)t * DD))[lane];
    float4 b = ((const float4*)(beta  + (size_t)t * DD))[lane];
    float o0 = fmaxf((v.x - mu) * rs * g.x + b.x, 0.0f);
    float o1 = fmaxf((v.y - mu) * rs * g.y + b.y, 0.0f);
    float o2 = fmaxf((v.z - mu) * rs * g.z + b.z, 0.0f);
    float o3 = fmaxf((v.w - mu) * rs * g.w + b.w, 0.0f);
    uint2 pw;
    pw.x = pack2(o0, o1);
    pw.y = pack2(o2, o3);
    ((uint2*)(g_yh + (size_t)gwarp * DD))[lane] = pw;
}

// Fused: scatter edges into (r,tile64) buckets; scatter node ids into type regions.
__global__ void scatter_kernel(const int* __restrict__ esrc,
                               const int* __restrict__ edst,
                               const int* __restrict__ etype,
                               const int* __restrict__ ntype,
                               int E, int N, int tiles) {
    int i = blockIdx.x * blockDim.x + threadIdx.x;
    if (i < E) {
        int d = edst[i];
        int b = etype[i] * tiles + (d >> 6);
        int pos = atomicAdd(&g_bcnt[b], 1);
        if (pos < CAP)
            g_ebuf[((size_t)b << 9) + pos] = ((d & 63) << 16) | esrc[i];
    }
    if (i < N) {
        int t = ntype[i];
        int p = atomicAdd(&g_tcnt[t], 1);
        g_perm[t * NMAX + p] = i;
    }
}

// ---------------- GEMM geometry ----------------
#define AHS   136
// conv: M-tile 64, N=K=128, 256 threads (8 warps), warp grid 2(M)x4(N),
// warp tile 32x32 -> acc = 32 regs/thread. 2 CTAs/SM for phase overlap.
#define SL_OFF  ((TROWS + 128) * AHS)           // halves offset of slist
#define CONV_SMEM ((TROWS + 128) * AHS * 2 + 4096 * 2 + 520 * 4 + 512 * 4 + 256 * 4 + 256 * 4 + 512 * 2)
#define CTHR  256
// MLP: M-tile 128, 512 threads (R15 geometry, unchanged)
#define MROWS 128
#define MLP_SMEM  (2 * 128 * AHS * 2)           // 69632 B
#define GTHR  512

// ---------------- fused conv GEMM ----------------
// CTA owns 64 dst rows (one tile64). Startup: micro bucket-sort of the tile's
// 8 relation-buckets into per-(r,row) smem CSR (slist/soff) + degree-sorted
// row order (rord). Then loops r = 0..8 (8 relations + root):
//   A_r[row] = sum over smem-listed srcs of y1[src]  (fp16 HADD2, prefetched)
//   acc += A_r @ W_r^T  (fp32 register accumulation)
// Epilogue: x1[row] = x[row] + acc[row].
__global__ __launch_bounds__(CTHR, 2)
void conv_gemm_kernel(const float* __restrict__ x,
                      const float* __restrict__ W_rel,
                      const float* __restrict__ W_root,
                      int N, int tiles) {
    extern __shared__ __half smh[];
    __half (*As)[AHS] = (__half (*)[AHS])smh;                     // 64 rows
    __half (*Bs)[AHS] = (__half (*)[AHS])(smh + TROWS * AHS);     // 128 rows
    uint16_t* slist = (uint16_t*)(smh + SL_OFF);     // 4096
    int* soff = (int*)(slist + 4096);                // 513 used (pad 520)
    int* hcur = soff + 520;                          // 512
    int* dcnt = hcur + 512;                          // 256 (8 r x 32 deg bins)
    int* dcur = dcnt + 256;                          // 256
    uint16_t* rord = (uint16_t*)(dcur + 256);        // 512
    __shared__ int wsum[8];

    const int tid  = threadIdx.x;
    const int wid  = tid >> 5;
    const int wm   = wid & 1;      // 2 M groups x 32 rows
    const int wn   = wid >> 1;     // 4 N groups x 32 cols
    const int lane = tid & 31;
    const int g    = lane >> 2;
    const int q    = lane & 3;
    const int tile = blockIdx.x;
    const int m0   = tile * TROWS;

    // ================= micro bucket sort =================
    for (int i = tid; i < 512; i += CTHR) hcur[i] = 0;
    if (tid < 256) dcnt[tid] = 0;
    __syncthreads();
    int bcnt[RR];
    #pragma unroll
    for (int r = 0; r < RR; r++) {
        int c = g_bcnt[r * tiles + tile];
        bcnt[r] = (c < CAP) ? c : CAP;
    }
    #pragma unroll
    for (int r = 0; r < RR; r++) {
        const int* eb = g_ebuf + ((size_t)(r * tiles + tile) << 9);
        for (int i = tid; i < bcnt[r]; i += CTHR)
            atomicAdd(&hcur[r * TROWS + (eb[i] >> 16)], 1);
    }
    __syncthreads();
    // exclusive scan over 512 bins (2 per thread)
    {
        int v0 = hcur[2 * tid], v1 = hcur[2 * tid + 1];
        int s = v0 + v1;
        int xv = s;
        #pragma unroll
        for (int d = 1; d < 32; d <<= 1) {
            int n = __shfl_up_sync(0xFFFFFFFFu, xv, d);
            if (lane >= d) xv += n;
        }
        if (lane == 31) wsum[wid] = xv;
        __syncthreads();
        if (tid == 0) {
            int run = 0;
            #pragma unroll
            for (int w = 0; w < 8; w++) { int y = wsum[w]; wsum[w] = run; run += y; }
        }
        __syncthreads();
        int excl = xv - s + wsum[wid];
        __syncthreads();            // everyone read hcur before overwrite
        soff[2 * tid] = excl;
        soff[2 * tid + 1] = excl + v0;
        hcur[2 * tid] = excl;
        hcur[2 * tid + 1] = excl + v0;
        if (tid == CTHR - 1) soff[512] = excl + s;
    }
    __syncthreads();
    // scatter srcs into sorted lists
    #pragma unroll
    for (int r = 0; r < RR; r++) {
        const int* eb = g_ebuf + ((size_t)(r * tiles + tile) << 9);
        for (int i = tid; i < bcnt[r]; i += CTHR) {
            int pk = eb[i];
            int p = atomicAdd(&hcur[r * TROWS + (pk >> 16)], 1);
            slist[p] = (uint16_t)(pk & 0xFFFF);
        }
    }
    // degree histogram per relation (512 bins / 256 threads = 2 each)
    #pragma unroll
    for (int k = 0; k < 2; k++) {
        const int bin = 2 * tid + k;
        int deg = soff[bin + 1] - soff[bin];
        int dc = (deg < 31) ? deg : 31;
        atomicAdd(&dcnt[(bin >> 6) * 32 + dc], 1);
    }
    __syncthreads();
    // per-relation exclusive scan of 32 degree bins (warp w handles r=w)
    if (wid < 8) {
        int v = dcnt[wid * 32 + lane];
        int xv = v;
        #pragma unroll
        for (int d = 1; d < 32; d <<= 1) {
            int n = __shfl_up_sync(0xFFFFFFFFu, xv, d);
            if (lane >= d) xv += n;
        }
        dcur[wid * 32 + lane] = xv - v;
    }
    __syncthreads();
    // scatter rows into degree-sorted order
    #pragma unroll
    for (int k = 0; k < 2; k++) {
        const int bin = 2 * tid + k;
        int deg = soff[bin + 1] - soff[bin];
        int dc = (deg < 31) ? deg : 31;
        const int r = bin >> 6;
        int pos = atomicAdd(&dcur[r * 32 + dc], 1);
        rord[r * TROWS + pos] = (uint16_t)(bin & 63);
    }

    // ================= GEMM =================
    const int grow = tid >> 2;            // row (0..63)
    const int part = tid & 3;             // 16B chunk id within 64B group
    const int bk   = tid >> 1;            // B k-row (0..127)
    const int bq   = (tid & 1) * 64;      // B n-half (64 floats)

    const uint32_t as_b = smem_u32(As);
    const uint32_t bs_b = smem_u32(Bs);
    uint32_t aaddr[2];
    #pragma unroll
    for (int mt = 0; mt < 2; mt++)
        aaddr[mt] = as_b + (uint32_t)(wm * 32 + mt * 16 + (lane & 15)) * (AHS * 2)
                         + (uint32_t)((lane >> 4) * 8) * 2;
    uint32_t baddr[2];
    #pragma unroll
    for (int grp = 0; grp < 2; grp++)
        baddr[grp] = bs_b + (uint32_t)((lane & 7) + ((lane >> 3) & 1) * 8) * (AHS * 2)
                          + (uint32_t)(wn * 32 + grp * 16 + (lane >> 4) * 8) * 2;

    float acc[2][4][4];
    #pragma unroll
    for (int mt = 0; mt < 2; mt++)
        #pragma unroll
        for (int nt = 0; nt < 4; nt++)
            #pragma unroll
            for (int rr = 0; rr < 4; rr++) acc[mt][nt][rr] = 0.0f;

    __syncthreads();   // sorted lists + rord visible

    const int m_g = m0 + grow;

    for (int r = 0; r < 9; r++) {
        // ---- stage A: one row per thread, prefetched edge pipeline ----
        if (r == 8) {
            #pragma unroll
            for (int j = 0; j < 4; j++) {
                uint4 u = make_uint4(0, 0, 0, 0);
                if (m_g < N) u = ((const uint4*)(g_yh + (size_t)m_g * DD))[(j << 2) + part];
                *(uint4*)&As[grow][j * 32 + part * 8] = u;
            }
        } else {
            const int srow = rord[r * TROWS + grow];
            const int bin = r * TROWS + srow;
            int p = soff[bin];
            const int e = soff[bin + 1];
            uint32_t h[16];
            #pragma unroll
            for (int j = 0; j < 16; j++) h[j] = 0;
            uint4 cu[4];
            if (p < e) {
                const uint4* yr = (const uint4*)(g_yh + (size_t)slist[p] * DD);
                #pragma unroll
                for (int j = 0; j < 4; j++) cu[j] = yr[(j << 2) + part];
            }
            while (p < e) {
                uint4 nu[4];
                if (p + 1 < e) {
                    const uint4* yn = (const uint4*)(g_yh + (size_t)slist[p + 1] * DD);
                    #pragma unroll
                    for (int j = 0; j < 4; j++) nu[j] = yn[(j << 2) + part];
                }
                #pragma unroll
                for (int j = 0; j < 4; j++) {
                    h[j*4+0] = hadd2u(h[j*4+0], cu[j].x);
                    h[j*4+1] = hadd2u(h[j*4+1], cu[j].y);
                    h[j*4+2] = hadd2u(h[j*4+2], cu[j].z);
                    h[j*4+3] = hadd2u(h[j*4+3], cu[j].w);
                }
                #pragma unroll
                for (int j = 0; j < 4; j++) cu[j] = nu[j];
                p++;
            }
            #pragma unroll
            for (int j = 0; j < 4; j++) {
                uint4 u = make_uint4(h[j*4+0], h[j*4+1], h[j*4+2], h[j*4+3]);
                *(uint4*)&As[srow][j * 32 + part * 8] = u;
            }
        }

        // ---- stage B: Bs[k][n] = W[k][n] (row-major, coalesced) ----
        const float* W = (r < 8) ? (W_rel + (size_t)r * DD * DD) : W_root;
        {
            const float4* wr = (const float4*)(W + (size_t)bk * DD + bq);
            #pragma unroll
            for (int jj = 0; jj < 8; jj++) {
                float4 v0 = wr[2 * jj];
                float4 v1 = wr[2 * jj + 1];
                uint4 u;
                u.x = pack2(v0.x, v0.y);
                u.y = pack2(v0.z, v0.w);
                u.z = pack2(v1.x, v1.y);
                u.w = pack2(v1.z, v1.w);
                *(uint4*)&Bs[bk][bq + jj * 8] = u;
            }
        }
        __syncthreads();

        // ---- MMA sweep: K=128 in 8 steps of k16 ----
        #pragma unroll
        for (int ks = 0; ks < 8; ks++) {
            uint32_t af[2][4];
            #pragma unroll
            for (int mt = 0; mt < 2; mt++) ldmx4(af[mt], aaddr[mt] + ks * 32);
            uint32_t bf[2][4];
            #pragma unroll
            for (int grp = 0; grp < 2; grp++) ldmx4t(bf[grp], baddr[grp] + ks * 16 * (AHS * 2));
            #pragma unroll
            for (int mt = 0; mt < 2; mt++)
                #pragma unroll
                for (int nt = 0; nt < 4; nt++)
                    mma_f16(acc[mt][nt], af[mt],
                            bf[nt >> 1][(nt & 1) * 2], bf[nt >> 1][(nt & 1) * 2 + 1]);
        }
        __syncthreads();
    }

    // epilogue: x1 = x + acc
    #pragma unroll
    for (int mt = 0; mt < 2; mt++) {
        #pragma unroll
        for (int half8 = 0; half8 < 2; half8++) {
            const int rl = wm * 32 + mt * 16 + half8 * 8 + g;
            const int m  = m0 + rl;
            if (m >= N) continue;
            const size_t base = (size_t)m * DD;
            #pragma unroll
            for (int nt = 0; nt < 4; nt++) {
                const int col = wn * 32 + nt * 8 + q * 2;
                float2 ad = *(const float2*)&x[base + col];
                float2 o;
                o.x = acc[mt][nt][half8 * 2 + 0] + ad.x;
                o.y = acc[mt][nt][half8 * 2 + 1] + ad.y;
                *(float2*)&g_x1[base + col] = o;
            }
        }
    }
}

// ---------------- MLP GEMM (type-bucketed, unchanged geometry) ----------------
// out[perm_row] = x1[perm_row] + b_mlp[t] + y2[perm_row] @ W_mlp[t]
__global__ __launch_bounds__(GTHR, 1)
void mlp_gemm_kernel(const float* __restrict__ W_mlp,
                     const float* __restrict__ biasp,
                     float* __restrict__ out,
                     int N) {
    const int ty  = blockIdx.y;
    const int Mloc = g_tcnt[ty];
    const int m0 = blockIdx.x * MROWS;
    if (m0 >= Mloc) return;

    extern __shared__ __half smh[];
    __half (*As)[AHS] = (__half (*)[AHS])smh;
    __half (*Bs)[AHS] = (__half (*)[AHS])(smh + 128 * AHS);

    const int tid  = threadIdx.x;
    const int wid  = tid >> 5;
    const int wm   = wid & 3;
    const int wn   = wid >> 2;
    const int lane = tid & 31;
    const int g    = lane >> 2;
    const int q    = lane & 3;

    const int* perm = g_perm + ty * NMAX;
    const float* W = W_mlp + (size_t)ty * DD * DD;
    const float* bias = biasp + (size_t)ty * DD;

    const int grow = tid >> 2;
    const int part = tid & 3;
    const int bk   = tid >> 2;
    const int bq   = (tid & 3) * 32;

    const uint32_t as_b = smem_u32(As);
    const uint32_t bs_b = smem_u32(Bs);
    uint32_t aaddr[2];
    #pragma unroll
    for (int mt = 0; mt < 2; mt++)
        aaddr[mt] = as_b + (uint32_t)(wm * 32 + mt * 16 + (lane & 15)) * (AHS * 2)
                         + (uint32_t)((lane >> 4) * 8) * 2;
    uint32_t baddr[2];
    #pragma unroll
    for (int grp = 0; grp < 2; grp++)
        baddr[grp] = bs_b + (uint32_t)((lane & 7) + ((lane >> 3) & 1) * 8) * (AHS * 2)
                          + (uint32_t)(wn * 32 + grp * 16 + (lane >> 4) * 8) * 2;

    // stage A: y2 row via perm (direct fp16 copy, one row per thread)
    {
        const int ga = m0 + grow;
        const int arow = (ga < Mloc) ? perm[ga] : -1;
        #pragma unroll
        for (int j = 0; j < 4; j++) {
            uint4 u = make_uint4(0, 0, 0, 0);
            if (arow >= 0) u = ((const uint4*)(g_yh + (size_t)arow * DD))[(j << 2) + part];
            *(uint4*)&As[grow][j * 32 + part * 8] = u;
        }
    }
    // stage B
    {
        const float4* wr = (const float4*)(W + (size_t)bk * DD + bq);
        #pragma unroll
        for (int jj = 0; jj < 4; jj++) {
            float4 v0 = wr[2 * jj];
            float4 v1 = wr[2 * jj + 1];
            uint4 u;
            u.x = pack2(v0.x, v0.y);
            u.y = pack2(v0.z, v0.w);
            u.z = pack2(v1.x, v1.y);
            u.w = pack2(v1.z, v1.w);
            *(uint4*)&Bs[bk][bq + jj * 8] = u;
        }
    }
    __syncthreads();

    float acc[2][4][4];
    #pragma unroll
    for (int mt = 0; mt < 2; mt++)
        #pragma unroll
        for (int nt = 0; nt < 4; nt++)
            #pragma unroll
            for (int rr = 0; rr < 4; rr++) acc[mt][nt][rr] = 0.0f;

    #pragma unroll
    for (int ks = 0; ks < 8; ks++) {
        uint32_t af[2][4];
        #pragma unroll
        for (int mt = 0; mt < 2; mt++) ldmx4(af[mt], aaddr[mt] + ks * 32);
        uint32_t bf[2][4];
        #pragma unroll
        for (int grp = 0; grp < 2; grp++) ldmx4t(bf[grp], baddr[grp] + ks * 16 * (AHS * 2));
        #pragma unroll
        for (int mt = 0; mt < 2; mt++)
            #pragma unroll
            for (int nt = 0; nt < 4; nt++)
                mma_f16(acc[mt][nt], af[mt],
                        bf[nt >> 1][(nt & 1) * 2], bf[nt >> 1][(nt & 1) * 2 + 1]);
    }

    #pragma unroll
    for (int mt = 0; mt < 2; mt++) {
        #pragma unroll
        for (int half8 = 0; half8 < 2; half8++) {
            const int rl  = wm * 32 + mt * 16 + half8 * 8 + g;
            const int grr = m0 + rl;
            if (grr >= Mloc) continue;
            const int prow = perm[grr];
            const size_t base = (size_t)prow * DD;
            #pragma unroll
            for (int nt = 0; nt < 4; nt++) {
                const int col = wn * 32 + nt * 8 + q * 2;
                float2 ad = *(const float2*)&g_x1[base + col];
                float2 bb = *(const float2*)&bias[col];
                float2 o;
                o.x = acc[mt][nt][half8 * 2 + 0] + ad.x + bb.x;
                o.y = acc[mt][nt][half8 * 2 + 1] + ad.y + bb.y;
                *(float2*)&out[base + col] = o;
            }
        }
    }
}

// ---------------- host launcher ----------------
extern "C" void kernel_launch(void* const* d_in, const int* in_sizes, int n_in,
                              void* d_out, int out_size) {
    const float* x          = (const float*)d_in[0];
    const int*   edge_src   = (const int*)  d_in[1];
    const int*   edge_dst   = (const int*)  d_in[2];
    const int*   node_type  = (const int*)  d_in[3];
    const int*   edge_type  = (const int*)  d_in[4];
    const float* conv_gamma = (const float*)d_in[5];
    const float* conv_beta  = (const float*)d_in[6];
    const float* W_rel      = (const float*)d_in[7];
    const float* W_root     = (const float*)d_in[8];
    const float* mlp_gamma  = (const float*)d_in[9];
    const float* mlp_beta   = (const float*)d_in[10];
    const float* W_mlp      = (const float*)d_in[11];
    const float* b_mlp      = (const float*)d_in[12];
    float* out = (float*)d_out;

    const int N      = in_sizes[0] / DD;
    const int E      = in_sizes[1];
    const int tiles  = (N + TROWS - 1) / TROWS;       // 64-row tiles (conv)
    const int mtiles = (N + MROWS - 1) / MROWS;       // 128-row tiles (mlp)

    static int attr_done = 0;
    if (!attr_done) {
        cudaFuncSetAttribute(conv_gemm_kernel,
                             cudaFuncAttributeMaxDynamicSharedMemorySize, CONV_SMEM);
        cudaFuncSetAttribute(mlp_gemm_kernel,
                             cudaFuncAttributeMaxDynamicSharedMemorySize, MLP_SMEM);
        attr_done = 1;
    }

    const int THR = 256;
    dim3 blk(THR);

    // launch 0: zero bucket + type counters (tiny)
    zero_kernel<<<(RR * tiles + THR - 1) / THR, blk>>>(RR * tiles);

    // launch 1: y1 = relu(LN(x)) with conv affine
    ln_relu_kernel<<<(N + 7) / 8, blk>>>(x, node_type, conv_gamma, conv_beta, N, 0);

    // launch 2: scatter edges into (r,tile64) buckets + nodes into type regions
    scatter_kernel<<<(E + THR - 1) / THR, blk>>>(edge_src, edge_dst, edge_type,
                                                 node_type, E, N, tiles);

    // launch 3 (ncu capture slot): fused conv, 2 CTAs/SM
    conv_gemm_kernel<<<tiles, CTHR, CONV_SMEM>>>(x, W_rel, W_root, N, tiles);

    // launch 4: y2 = relu(LN(x1)) with mlp affine
    ln_relu_kernel<<<(N + 7) / 8, blk>>>(x, node_type, mlp_gamma, mlp_beta, N, 1);

    // launch 5: MLP
    mlp_gemm_kernel<<<dim3(mtiles, TTY), GTHR, MLP_SMEM>>>(W_mlp, b_mlp, out, N);
}